// round 8
// baseline (speedup 1.0000x reference)
#include <cuda_runtime.h>
#include <cstddef>

// BinaryMaskEdgeSmoothing — exact integer-combinatorics reduction (validated,
// rel_err=0.0):
//   S9 = 3x3 sum, edges = 9*c - S9, n = Gauss numerator = S9 + m3 + vcen
//   out = (n + (|edges| < 5.5 ? c : 0)) > 8.5
// R8 == R7 resubmission (R7 never ran: broker GPUAcquisitionTimeout).
// Keep R6's one-iteration prefetch + __stcs (WIN: 92.6->88.1us); cut pipeline
// register footprint: float4-only row buffers, halos reconstructed at consume
// time via SHFL of register-resident column sums + predicated L1-hit patch
// loads on warp-edge lanes. Goal: regs 39->~33, occ 67->~80%.

#define Wd 1024
#define Hd 1024
#define RPT 16   // output rows per thread

__device__ __forceinline__ float4 load_row4(const float* __restrict__ base,
                                            int r, int j) {
    if ((unsigned)r >= (unsigned)Hd)              // SAME zero padding
        return make_float4(0.f, 0.f, 0.f, 0.f);
    return __ldg((const float4*)(base + (size_t)r * Wd + (j << 2)));
}

__device__ __forceinline__ float ldg_guard(const float* __restrict__ base,
                                           int r, int col) {
    return ((unsigned)r < (unsigned)Hd) ? __ldg(base + (size_t)r * Wd + col) : 0.f;
}

__global__ void __launch_bounds__(256)
mask_smooth_kernel(const float* __restrict__ in, float* __restrict__ out) {
    const int img  = blockIdx.y;
    const int r0   = blockIdx.x * RPT;
    const int j    = threadIdx.x;                 // float4 column index 0..255
    const int lane = threadIdx.x & 31;

    const float* base = in  + (size_t)img * Hd * Wd;
    float*       ob   = out + (size_t)img * Hd * Wd;

    float4 a4 = load_row4(base, r0 - 1, j);       // rows r-1, r, r+1
    float4 b4 = load_row4(base, r0,     j);
    float4 c4 = load_row4(base, r0 + 1, j);

    #pragma unroll
    for (int rr = 0; rr < RPT; ++rr) {
        const int r = r0 + rr;

        // Prefetch next iteration's bottom row FIRST (DRAM latency shadow).
        float4 n4 = load_row4(base, r + 2, j);

        // Vertical column sums for the 4 owned columns.
        float cs0 = a4.x + b4.x + c4.x;
        float cs1 = a4.y + b4.y + c4.y;
        float cs2 = a4.z + b4.z + c4.z;
        float cs3 = a4.w + b4.w + c4.w;

        // Halo column sums + middle-row halos via warp shuffle of
        // register-resident values (NOT in the load path).
        float csL = __shfl_up_sync(0xffffffffu,  cs3, 1);
        float csR = __shfl_down_sync(0xffffffffu, cs0, 1);
        float bL  = __shfl_up_sync(0xffffffffu,  b4.w, 1);
        float bR  = __shfl_down_sync(0xffffffffu, b4.x, 1);

        if (lane == 0) {                          // warp-left edge: L1-hit patch
            if (j > 0) {
                const int col = (j << 2) - 1;
                bL  = __ldg(base + (size_t)r * Wd + col);
                csL = ldg_guard(base, r - 1, col) + bL + ldg_guard(base, r + 1, col);
            } else { bL = 0.f; csL = 0.f; }       // image edge: zero pad
        }
        if (lane == 31) {                         // warp-right edge
            if (j < (Wd / 4 - 1)) {
                const int col = (j << 2) + 4;
                bR  = __ldg(base + (size_t)r * Wd + col);
                csR = ldg_guard(base, r - 1, col) + bR + ldg_guard(base, r + 1, col);
            } else { bR = 0.f; csR = 0.f; }
        }

        const float cs[6] = {csL, cs0, cs1, cs2, cs3, csR};
        const float bm[6] = {bL, b4.x, b4.y, b4.z, b4.w, bR};

        float res[4];
        #pragma unroll
        for (int i = 0; i < 4; ++i) {
            float S9    = cs[i] + cs[i + 1] + cs[i + 2];
            float m3    = bm[i] + bm[i + 1] + bm[i + 2];
            float cv    = bm[i + 1];
            float vcen  = cs[i + 1] + cv;         // t_c + 2*m_c + b_c
            float nG    = S9 + m3 + vcen;         // Gauss numerator, 0..16
            float edges = fmaf(9.f, cv, -S9);     // Laplacian response, -9..9
            float bonus = (fabsf(edges) < 5.5f) ? cv : 0.f;
            res[i] = (nG + bonus > 8.5f) ? 1.f : 0.f;
        }

        float4 o;
        o.x = res[0]; o.y = res[1]; o.z = res[2]; o.w = res[3];
        __stcs((float4*)(ob + (size_t)r * Wd + (j << 2)), o);   // streaming store

        a4 = b4; b4 = c4; c4 = n4;                // roll the window
    }
}

extern "C" void kernel_launch(void* const* d_in, const int* in_sizes, int n_in,
                              void* d_out, int out_size) {
    const float* mask = (const float*)d_in[0];    // [B*C, H, W] fp32 binary
    float*       outp = (float*)d_out;
    const int nimg = in_sizes[0] / (Hd * Wd);     // 64 for the reference shapes

    dim3 grid(Hd / RPT, nimg);
    mask_smooth_kernel<<<grid, 256>>>(mask, outp);
}

// round 11
// speedup vs baseline: 1.0576x; 1.0576x over previous
#include <cuda_runtime.h>
#include <cstddef>

// BinaryMaskEdgeSmoothing — exact integer-combinatorics reduction (validated,
// rel_err=0.0):
//   S9 = 3x3 sum, edges = 9*c - S9, n = Gauss numerator = S9 + m3 + vcen
//   out = (n + (|edges| < 5.5 ? c : 0)) > 8.5
// R11 == R9/R10 resubmission (neither ran: broker GPUAcquisitionTimeout).
// R6 body (prefetch + __stcs, committed 88.1us) + __launch_bounds__(256,7):
// ptxas reg budget 36 (was 39) -> 7 CTAs/SM instead of 6. R8's shuffle-halo
// restructure FAILED (regs 39->48); route abandoned.

#define Wd 1024
#define Hd 1024
#define RPT 16   // output rows per thread

__device__ __forceinline__ void load_row(const float* __restrict__ base, int r,
                                         int j, float v[6]) {
    if ((unsigned)r >= (unsigned)Hd) {            // SAME zero padding
        v[0] = v[1] = v[2] = v[3] = v[4] = v[5] = 0.f;
        return;
    }
    const float* p = base + (size_t)r * Wd + (j << 2);
    float4 cc = __ldg((const float4*)p);
    v[0] = (j > 0) ? __ldg(p - 1) : 0.f;          // left halo (L1-hit)
    v[1] = cc.x; v[2] = cc.y; v[3] = cc.z; v[4] = cc.w;
    v[5] = (j < (Wd / 4 - 1)) ? __ldg(p + 4) : 0.f;  // right halo (L1-hit)
}

__global__ void __launch_bounds__(256, 7)
mask_smooth_kernel(const float* __restrict__ in, float* __restrict__ out) {
    const int img = blockIdx.y;
    const int r0  = blockIdx.x * RPT;
    const int j   = threadIdx.x;                  // float4 column index 0..255

    const float* base = in  + (size_t)img * Hd * Wd;
    float*       ob   = out + (size_t)img * Hd * Wd;

    float a[6], b[6], c[6], n6[6];                // rows r-1, r, r+1, prefetch r+2
    load_row(base, r0 - 1, j, a);
    load_row(base, r0,     j, b);
    load_row(base, r0 + 1, j, c);

    #pragma unroll
    for (int rr = 0; rr < RPT; ++rr) {
        const int r = r0 + rr;

        // Prefetch next iteration's bottom row FIRST — its latency overlaps
        // this iteration's arithmetic + store.
        load_row(base, r + 2, j, n6);

        float cs[6];                              // vertical column sums
        #pragma unroll
        for (int k = 0; k < 6; ++k) cs[k] = a[k] + b[k] + c[k];

        float res[4];
        #pragma unroll
        for (int i = 0; i < 4; ++i) {
            float S9    = cs[i] + cs[i + 1] + cs[i + 2];
            float m3    = b[i]  + b[i + 1]  + b[i + 2];
            float cv    = b[i + 1];
            float vcen  = cs[i + 1] + cv;         // t_c + 2*m_c + b_c
            float nG    = S9 + m3 + vcen;         // Gauss numerator, 0..16
            float edges = fmaf(9.f, cv, -S9);     // Laplacian response, -9..9
            float bonus = (fabsf(edges) < 5.5f) ? cv : 0.f;
            res[i] = (nG + bonus > 8.5f) ? 1.f : 0.f;
        }

        float4 o;
        o.x = res[0]; o.y = res[1]; o.z = res[2]; o.w = res[3];
        __stcs((float4*)(ob + (size_t)r * Wd + (j << 2)), o);   // streaming store

        #pragma unroll
        for (int k = 0; k < 6; ++k) { a[k] = b[k]; b[k] = c[k]; c[k] = n6[k]; }
    }
}

extern "C" void kernel_launch(void* const* d_in, const int* in_sizes, int n_in,
                              void* d_out, int out_size) {
    const float* mask = (const float*)d_in[0];    // [B*C, H, W] fp32 binary
    float*       outp = (float*)d_out;
    const int nimg = in_sizes[0] / (Hd * Wd);     // 64 for the reference shapes

    dim3 grid(Hd / RPT, nimg);
    mask_smooth_kernel<<<grid, 256>>>(mask, outp);
}

// round 14
// speedup vs baseline: 1.1230x; 1.0619x over previous
#include <cuda_runtime.h>
#include <cstddef>

// BinaryMaskEdgeSmoothing — exact integer-combinatorics reduction (validated,
// rel_err=0.0):
//   S9 = 3x3 sum, edges = 9*c - S9, n = Gauss numerator = S9 + m3 + vcen
//   out = (n + (|edges| < 5.5 ? c : 0)) > 8.5
// R14 == R12/R13 resubmission (neither ran: broker GPUAcquisitionTimeout).
// Row-PAIR processing: per-warp batched MLP is the proven lever (R6/R8/R11
// curve). 2 output rows + 2 front-batched independent row prefetches per
// iteration (MLP_p1 1->2), shared bc=b+c partial sums, last-iter prefetch
// skipped, natural register allocation, __stcs streaming stores.

#define Wd 1024
#define Hd 1024
#define RPT 16   // output rows per thread (8 iterations x 2 rows)

__device__ __forceinline__ void load_row(const float* __restrict__ base, int r,
                                         int j, float v[6]) {
    if ((unsigned)r >= (unsigned)Hd) {            // SAME zero padding
        v[0] = v[1] = v[2] = v[3] = v[4] = v[5] = 0.f;
        return;
    }
    const float* p = base + (size_t)r * Wd + (j << 2);
    float4 cc = __ldg((const float4*)p);
    v[0] = (j > 0) ? __ldg(p - 1) : 0.f;          // left halo (L1-hit)
    v[1] = cc.x; v[2] = cc.y; v[3] = cc.z; v[4] = cc.w;
    v[5] = (j < (Wd / 4 - 1)) ? __ldg(p + 4) : 0.f;  // right halo (L1-hit)
}

// Decision for one output row given its 3-row column sums cs[6] and middle row m[6].
__device__ __forceinline__ void decide4(const float cs[6], const float m[6],
                                        float res[4]) {
    #pragma unroll
    for (int i = 0; i < 4; ++i) {
        float S9    = cs[i] + cs[i + 1] + cs[i + 2];
        float m3    = m[i]  + m[i + 1]  + m[i + 2];
        float cv    = m[i + 1];
        float vcen  = cs[i + 1] + cv;             // t_c + 2*m_c + b_c
        float nG    = S9 + m3 + vcen;             // Gauss numerator, 0..16
        float edges = fmaf(9.f, cv, -S9);         // Laplacian response, -9..9
        float bonus = (fabsf(edges) < 5.5f) ? cv : 0.f;
        res[i] = (nG + bonus > 8.5f) ? 1.f : 0.f;
    }
}

__global__ void __launch_bounds__(256)
mask_smooth_kernel(const float* __restrict__ in, float* __restrict__ out) {
    const int img = blockIdx.y;
    const int r0  = blockIdx.x * RPT;
    const int j   = threadIdx.x;                  // float4 column index 0..255

    const float* base = in  + (size_t)img * Hd * Wd;
    float*       ob   = out + (size_t)img * Hd * Wd;

    // Rolling window rows r-1..r+2 plus two prefetch buffers.
    float a[6], b[6], c[6], d[6], n1[6], n2[6];
    load_row(base, r0 - 1, j, a);
    load_row(base, r0,     j, b);
    load_row(base, r0 + 1, j, c);
    load_row(base, r0 + 2, j, d);

    #pragma unroll
    for (int it = 0; it < RPT / 2; ++it) {
        const int r = r0 + 2 * it;

        // Front-batched prefetch of the next pair's rows (2 independent
        // LDG.128 -> MLP_p1 = 2). Compile-time skipped on the last iteration
        // (those rows belong to the next strip).
        if (it < RPT / 2 - 1) {
            load_row(base, r + 3, j, n1);
            load_row(base, r + 4, j, n2);
        }

        float bc[6], cs0[6], cs1[6];
        #pragma unroll
        for (int k = 0; k < 6; ++k) {
            bc[k]  = b[k] + c[k];                 // shared by both output rows
            cs0[k] = a[k] + bc[k];                // rows r-1,r,r+1
            cs1[k] = bc[k] + d[k];                // rows r,r+1,r+2
        }

        float res0[4], res1[4];
        decide4(cs0, b, res0);                    // output row r   (middle = b)
        decide4(cs1, c, res1);                    // output row r+1 (middle = c)

        float4 o0, o1;
        o0.x = res0[0]; o0.y = res0[1]; o0.z = res0[2]; o0.w = res0[3];
        o1.x = res1[0]; o1.y = res1[1]; o1.z = res1[2]; o1.w = res1[3];
        __stcs((float4*)(ob + (size_t)r       * Wd + (j << 2)), o0);
        __stcs((float4*)(ob + (size_t)(r + 1) * Wd + (j << 2)), o1);

        #pragma unroll
        for (int k = 0; k < 6; ++k) {             // roll window by 2 rows
            a[k] = c[k]; b[k] = d[k]; c[k] = n1[k]; d[k] = n2[k];
        }
    }
}

extern "C" void kernel_launch(void* const* d_in, const int* in_sizes, int n_in,
                              void* d_out, int out_size) {
    const float* mask = (const float*)d_in[0];    // [B*C, H, W] fp32 binary
    float*       outp = (float*)d_out;
    const int nimg = in_sizes[0] / (Hd * Wd);     // 64 for the reference shapes

    dim3 grid(Hd / RPT, nimg);
    mask_smooth_kernel<<<grid, 256>>>(mask, outp);
}